// round 5
// baseline (speedup 1.0000x reference)
#include <cuda_runtime.h>
#include <math.h>

// ---------------------------------------------------------------------------
// ContextualAttention: B=2, C=128, H=W=128, RATE=2, BLOCK=3, SCALE=10, EPS=1e-4
//
// Round 5 (resubmit of untested Round 4 after infra flake):
//  * symmetric Gram GEMM (528/1024 blocks + mirrored float4 stores)
//  * fused scores + chunk-softmax (online max/sum), S written once
//  * soft3 emits sparse-only (no dense att write); spmm gathers patch values
//    straight from x (L2-resident) instead of a materialized 67 MB Vt.
//  * exactness: sparse flush at (score - colmax) <= -21 validated rel_err==0;
//    overflow fallback recomputes weights bit-identically from raw scores.
// ---------------------------------------------------------------------------

constexpr int Bn = 2, Cn = 128, Hn = 128, Wn = 128;
constexpr int HR = 64, Ln = 4096, F2 = 2048, KC = 128;
constexpr int PCH = 8;                 // p-chunks for partial softmax
constexpr int PCS = Ln / PCH;          // 512
constexpr int CAP = 128;               // sparse cap per column

// -------- static scratch (allocation-free rule) ----------------------------
__device__ float g_Xr [Bn][KC][Ln];    //   4 MB  (c,p) strided pixels
__device__ float g_G  [Bn][Ln][Ln];    // 134 MB  Gram (symmetric)
__device__ float g_S  [Bn][Ln][Ln];    // 134 MB  raw masked/scaled scores
__device__ float g_M2 [Bn][Ln][F2];    //  67 MB  (q,f)
__device__ float g_invd [Bn][Ln];
__device__ float g_w    [Bn][Ln];      // mfilt * invd (pre-softmax row factor)
__device__ float g_mfilt[Bn][Ln];
__device__ float g_pmax[Bn][PCH][Ln];
__device__ float g_psum[Bn][PCH][Ln];
__device__ float g_cmax[Bn][Ln];
__device__ float g_crcp[Bn][Ln];
__device__ int   g_cnt [Bn][Ln];
__device__ int   g_sp_p[Bn][Ln][CAP];
__device__ float g_sp_w[Bn][Ln][CAP];

// ---------------------------------------------------------------------------
__global__ void k_build_xr(const float* __restrict__ x) {
    int idx = blockIdx.x * blockDim.x + threadIdx.x;
    if (idx >= Bn * KC * Ln) return;
    int p = idx & (Ln - 1);
    int c = (idx >> 12) & (KC - 1);
    int b = idx >> 19;
    int py = p >> 6, px = p & 63;
    g_Xr[b][c][p] = x[((b * Cn + c) * Hn + 2 * py) * Wn + 2 * px];
}

__global__ void k_mfilt(const float* __restrict__ mask) {
    int idx = blockIdx.x * blockDim.x + threadIdx.x;
    if (idx >= Bn * Ln) return;
    int q = idx & (Ln - 1);
    int b = idx >> 12;
    g_cnt[b][q] = 0;                    // reset sparse counters every launch
    int qy = q >> 6, qx = q & 63;
    float s = 0.0f;
    #pragma unroll
    for (int dy = -1; dy <= 1; dy++)
        #pragma unroll
        for (int dx = -1; dx <= 1; dx++) {
            int yy = qy + dy, xx = qx + dx;
            if (yy >= 0 && yy < HR && xx >= 0 && xx < HR)
                s += mask[(b * Hn + 2 * yy) * Wn + 2 * xx];
        }
    g_mfilt[b][q] = ((s / 9.0f) == 0.0f) ? 1.0f : 0.0f;
}

// -------- GEMM 1: G = Xr^T * Xr, symmetric (upper-triangle blocks) ---------
__global__ void __launch_bounds__(256) k_gemm_G() {
    int b = blockIdx.z;
    // map linear pair index -> (bm, bn), bm <= bn, 32x32 block grid
    int rem = blockIdx.x, bm = 0;
    while (rem >= 32 - bm) { rem -= 32 - bm; bm++; }
    int bn = bm + rem;
    int m0 = bm << 7, n0 = bn << 7;

    __shared__ float As[8][128];
    __shared__ float Bs[8][128];
    int tid = threadIdx.x, ty = tid >> 4, tx = tid & 15;
    int lk = tid >> 5, ls = (tid & 31) << 2;
    const float* A = &g_Xr[b][0][0];

    float acc[8][8];
    #pragma unroll
    for (int i = 0; i < 8; i++)
        #pragma unroll
        for (int j = 0; j < 8; j++) acc[i][j] = 0.0f;

    for (int k0 = 0; k0 < KC; k0 += 8) {
        *(float4*)&As[lk][ls] = *(const float4*)&A[(k0 + lk) * Ln + m0 + ls];
        *(float4*)&Bs[lk][ls] = *(const float4*)&A[(k0 + lk) * Ln + n0 + ls];
        __syncthreads();
        #pragma unroll
        for (int kk = 0; kk < 8; kk++) {
            float a[8], bb[8];
            *(float4*)&a[0]  = *(float4*)&As[kk][ty << 2];
            *(float4*)&a[4]  = *(float4*)&As[kk][64 + (ty << 2)];
            *(float4*)&bb[0] = *(float4*)&Bs[kk][tx << 2];
            *(float4*)&bb[4] = *(float4*)&Bs[kk][64 + (tx << 2)];
            #pragma unroll
            for (int i = 0; i < 8; i++)
                #pragma unroll
                for (int j = 0; j < 8; j++) acc[i][j] += a[i] * bb[j];
        }
        __syncthreads();
    }
    // normal store (m0, n0)
    #pragma unroll
    for (int i = 0; i < 8; i++) {
        int m = m0 + ((i < 4) ? (ty << 2) + i : 60 + (ty << 2) + i);
        float4 c0 = make_float4(acc[i][0], acc[i][1], acc[i][2], acc[i][3]);
        float4 c1 = make_float4(acc[i][4], acc[i][5], acc[i][6], acc[i][7]);
        *(float4*)&g_G[b][m][n0 + (tx << 2)]      = c0;
        *(float4*)&g_G[b][m][n0 + 64 + (tx << 2)] = c1;
    }
    // mirrored store (n0, m0): G[n][m] = acc[i][j] with roles swapped
    if (bm != bn) {
        #pragma unroll
        for (int j = 0; j < 8; j++) {
            int n = n0 + ((j < 4) ? (tx << 2) + j : 60 + (tx << 2) + j);
            float4 r0 = make_float4(acc[0][j], acc[1][j], acc[2][j], acc[3][j]);
            float4 r1 = make_float4(acc[4][j], acc[5][j], acc[6][j], acc[7][j]);
            *(float4*)&g_G[b][n][m0 + (ty << 2)]      = r0;
            *(float4*)&g_G[b][n][m0 + 64 + (ty << 2)] = r1;
        }
    }
}

// -------- denom from diag of shifted G, + premultiplied row factor ---------
__global__ void k_diag() {
    int idx = blockIdx.x * blockDim.x + threadIdx.x;
    if (idx >= Bn * Ln) return;
    int p = idx & (Ln - 1);
    int b = idx >> 12;
    int py = p >> 6, px = p & 63;
    float acc = 0.0f;
    #pragma unroll
    for (int dy = -1; dy <= 1; dy++)
        #pragma unroll
        for (int dx = -1; dx <= 1; dx++) {
            int yy = py + dy, xx = px + dx;
            if (yy >= 0 && yy < HR && xx >= 0 && xx < HR) {
                int u = (yy << 6) + xx;
                acc += g_G[b][u][u];
            }
        }
    float inv = 10.0f / sqrtf(acc + 0.1152f);   // 1152 * 1e-4
    g_invd[b][p] = inv;
    g_w[b][p]    = inv * g_mfilt[b][p];
}

// -------- fused: scores (9-tap shift of G) + chunked online softmax --------
__global__ void __launch_bounds__(256) k_scores1() {
    int b = blockIdx.z;
    int q = (blockIdx.x << 8) + threadIdx.x;
    int p0 = blockIdx.y * PCS;
    int qy = q >> 6, qx = q & 63;

    float m = -3.0e38f, s = 0.0f;
    for (int p = p0; p < p0 + PCS; p++) {
        int py = p >> 6, px = p & 63;
        float acc = 0.0f;
        #pragma unroll
        for (int dy = -1; dy <= 1; dy++)
            #pragma unroll
            for (int dx = -1; dx <= 1; dx++) {
                bool ok = (py + dy >= 0) && (py + dy < HR) && (px + dx >= 0) && (px + dx < HR)
                       && (qy + dy >= 0) && (qy + dy < HR) && (qx + dx >= 0) && (qx + dx < HR);
                if (ok) {
                    int off = dy * 64 + dx;
                    acc += g_G[b][p + off][q + off];
                }
            }
        float v = g_w[b][p] * acc;
        g_S[b][p][q] = v;
        if (v > m) { s *= __expf(m - v); m = v; }
        float d = v - m;
        if (d > -21.0f) s += __expf(d);   // exp(-21) ~ 7.6e-10: negligible mass
    }
    g_pmax[b][blockIdx.y][q] = m;
    g_psum[b][blockIdx.y][q] = s;
}

__global__ void k_soft2() {
    int idx = blockIdx.x * blockDim.x + threadIdx.x;
    if (idx >= Bn * Ln) return;
    int q = idx & (Ln - 1);
    int b = idx >> 12;
    float m = -3.0e38f;
    #pragma unroll
    for (int ch = 0; ch < PCH; ch++) m = fmaxf(m, g_pmax[b][ch][q]);
    float s = 0.0f;
    #pragma unroll
    for (int ch = 0; ch < PCH; ch++) s += g_psum[b][ch][q] * __expf(g_pmax[b][ch][q] - m);
    g_cmax[b][q] = m;
    g_crcp[b][q] = 1.0f / s;
}

// -------- sparse emission only (reads raw scores; no dense att write) ------
__global__ void __launch_bounds__(256) k_soft3() {
    int b = blockIdx.z;
    int q = (blockIdx.x << 8) + threadIdx.x;
    int p0 = blockIdx.y * PCS;
    float cm = g_cmax[b][q];
    float cr = g_crcp[b][q];
    for (int p = p0; p < p0 + PCS; p++) {
        float d = g_S[b][p][q] - cm;
        if (d > -21.0f) {
            float w = __expf(d) * cr * g_mfilt[b][p];
            if (w != 0.0f) {
                int slot = atomicAdd(&g_cnt[b][q], 1);
                if (slot < CAP) {
                    g_sp_p[b][q][slot] = p;
                    g_sp_w[b][q][slot] = w;
                }
            }
        }
    }
}

// -------- patch-value gather straight from x (L2-resident, 8 MB) -----------
__device__ __forceinline__ float vt_val(const float* __restrict__ x,
                                        int b, int p, int f) {
    int c = f >> 4, i = (f >> 2) & 3, j = f & 3;
    int py = p >> 6, px = p & 63;
    int r  = 2 * py - 1 + i;
    int cc = 2 * px - 1 + j;
    return (r >= 0 && r < Hn && cc >= 0 && cc < Wn)
         ? x[((b * Cn + c) * Hn + r) * Wn + cc] : 0.0f;
}

// -------- SpMM: M2[q][:] = sum_k w_k * V[p_k][:] ---------------------------
__global__ void __launch_bounds__(256) k_spmm(const float* __restrict__ x) {
    int q = blockIdx.x, b = blockIdx.y;
    int tid = threadIdx.x;
    __shared__ int   s_p[CAP];
    __shared__ float s_w[CAP];
    int cnt = g_cnt[b][q];

    float acc[8];
    #pragma unroll
    for (int i = 0; i < 8; i++) acc[i] = 0.0f;

    if (cnt <= CAP) {
        if (tid < cnt) { s_p[tid] = g_sp_p[b][q][tid]; s_w[tid] = g_sp_w[b][q][tid]; }
        __syncthreads();
        if (tid == 0 && cnt > 1) {        // deterministic order: sort by p
            for (int i = 1; i < cnt; i++) {
                int   kp = s_p[i]; float kw = s_w[i];
                int j = i - 1;
                while (j >= 0 && s_p[j] > kp) { s_p[j+1] = s_p[j]; s_w[j+1] = s_w[j]; j--; }
                s_p[j+1] = kp; s_w[j+1] = kw;
            }
        }
        __syncthreads();
        for (int k = 0; k < cnt; k++) {
            float w = s_w[k];
            int   p = s_p[k];
            #pragma unroll
            for (int i = 0; i < 8; i++) acc[i] += w * vt_val(x, b, p, tid + (i << 8));
        }
    } else {
        // exact dense fallback: recompute weights from raw scores, ascending p
        float cm = g_cmax[b][q];
        float cr = g_crcp[b][q];
        for (int p = 0; p < Ln; p++) {
            float d = g_S[b][p][q] - cm;
            if (d > -21.0f) {
                float w = __expf(d) * cr * g_mfilt[b][p];
                if (w != 0.0f) {
                    #pragma unroll
                    for (int i = 0; i < 8; i++) acc[i] += w * vt_val(x, b, p, tid + (i << 8));
                }
            }
        }
    }
    #pragma unroll
    for (int i = 0; i < 8; i++) g_M2[b][q][tid + (i << 8)] = acc[i];
}

// -------- overlap-add (transposed-conv scatter, gathered) ------------------
__global__ void k_out(float* __restrict__ out) {
    int idx = blockIdx.x * blockDim.x + threadIdx.x;
    if (idx >= Bn * Cn * Hn * Wn) return;
    int X = idx & 127;
    int Y = (idx >> 7) & 127;
    int c = (idx >> 14) & 127;
    int b = idx >> 21;
    int i0 = (Y + 1) & 1, j0 = (X + 1) & 1;
    float acc = 0.0f;
    #pragma unroll
    for (int a = 0; a < 2; a++) {
        int i = i0 + 2 * a;
        int qy = (Y + 1 - i) >> 1;
        if (qy < 0 || qy >= HR) continue;
        #pragma unroll
        for (int e = 0; e < 2; e++) {
            int j = j0 + 2 * e;
            int qx = (X + 1 - j) >> 1;
            if (qx < 0 || qx >= HR) continue;
            acc += g_M2[b][(qy << 6) + qx][(c << 4) + (i << 2) + j];
        }
    }
    out[idx] = 0.25f * acc;
}

// ---------------------------------------------------------------------------
extern "C" void kernel_launch(void* const* d_in, const int* in_sizes, int n_in,
                              void* d_out, int out_size) {
    const float* x    = (const float*)d_in[0];
    const float* mask = (const float*)d_in[1];
    if (n_in >= 2 && in_sizes[0] < in_sizes[1]) {   // defensive: x is the big one
        const float* t = x; x = mask; mask = t;
    }
    float* out = (float*)d_out;

    k_build_xr<<<(Bn * KC * Ln) / 256, 256>>>(x);
    k_mfilt   <<<(Bn * Ln) / 256, 256>>>(mask);

    k_gemm_G  <<<dim3(528, 1, Bn), 256>>>();
    k_diag    <<<(Bn * Ln) / 256, 256>>>();

    k_scores1 <<<dim3(Ln / 256, PCH, Bn), 256>>>();
    k_soft2   <<<(Bn * Ln) / 256, 256>>>();
    k_soft3   <<<dim3(Ln / 256, PCH, Bn), 256>>>();

    k_spmm    <<<dim3(Ln, Bn), 256>>>(x);
    k_out     <<<(Bn * Cn * Hn * Wn) / 256, 256>>>(out);
}

// round 6
// speedup vs baseline: 2.7223x; 2.7223x over previous
#include <cuda_runtime.h>
#include <math.h>

// ---------------------------------------------------------------------------
// ContextualAttention: B=2, C=128, H=W=128, RATE=2, BLOCK=3, SCALE=10, EPS=1e-4
//
// Round 6: no score matrix at all.
//   G = Xr^T Xr (symmetric gemm, 528/1024 blocks)
//   lb[q] = diagonal score v_qq (>= colmax - 0.02 by Cauchy-Schwarz) is the
//   softmax reference: emit (p, exp(v - lb)) for v - lb > -21 (conservative
//   subset of the rel_err==0-validated colmax flush). One-element-per-thread
//   everywhere (the R5 regression was latency-bound 512-iteration loops).
//   spmm: deterministic sorted sum of the tiny list, value gather from x.
// ---------------------------------------------------------------------------

constexpr int Bn = 2, Cn = 128, Hn = 128, Wn = 128;
constexpr int HR = 64, Ln = 4096, F2 = 2048, KC = 128;
constexpr int CAP = 128;               // sparse cap per column

// -------- static scratch (allocation-free rule) ----------------------------
__device__ float g_Xr [Bn][KC][Ln];    //   4 MB  (c,p) strided pixels
__device__ float g_G  [Bn][Ln][Ln];    // 134 MB  Gram (symmetric)
__device__ float g_M2 [Bn][Ln][F2];    //  67 MB  (q,f)
__device__ float g_w    [Bn][Ln];      // mfilt * 10/denom (row factor)
__device__ float g_lb   [Bn][Ln];      // diagonal score = softmax reference
__device__ float g_mfilt[Bn][Ln];
__device__ int   g_cnt [Bn][Ln];
__device__ int   g_sp_p[Bn][Ln][CAP];
__device__ float g_sp_w[Bn][Ln][CAP];

// ---------------------------------------------------------------------------
__global__ void k_build_xr(const float* __restrict__ x) {
    int idx = blockIdx.x * blockDim.x + threadIdx.x;
    if (idx >= Bn * KC * Ln) return;
    int p = idx & (Ln - 1);
    int c = (idx >> 12) & (KC - 1);
    int b = idx >> 19;
    int py = p >> 6, px = p & 63;
    g_Xr[b][c][p] = x[((b * Cn + c) * Hn + 2 * py) * Wn + 2 * px];
}

__global__ void k_mfilt(const float* __restrict__ mask) {
    int idx = blockIdx.x * blockDim.x + threadIdx.x;
    if (idx >= Bn * Ln) return;
    int q = idx & (Ln - 1);
    int b = idx >> 12;
    g_cnt[b][q] = 0;                    // reset sparse counters every launch
    int qy = q >> 6, qx = q & 63;
    float s = 0.0f;
    #pragma unroll
    for (int dy = -1; dy <= 1; dy++)
        #pragma unroll
        for (int dx = -1; dx <= 1; dx++) {
            int yy = qy + dy, xx = qx + dx;
            if (yy >= 0 && yy < HR && xx >= 0 && xx < HR)
                s += mask[(b * Hn + 2 * yy) * Wn + 2 * xx];
        }
    g_mfilt[b][q] = ((s / 9.0f) == 0.0f) ? 1.0f : 0.0f;
}

// -------- GEMM 1: G = Xr^T * Xr, symmetric (upper-triangle blocks) ---------
__global__ void __launch_bounds__(256) k_gemm_G() {
    int b = blockIdx.z;
    int rem = blockIdx.x, bm = 0;
    while (rem >= 32 - bm) { rem -= 32 - bm; bm++; }
    int bn = bm + rem;
    int m0 = bm << 7, n0 = bn << 7;

    __shared__ float As[8][128];
    __shared__ float Bs[8][128];
    int tid = threadIdx.x, ty = tid >> 4, tx = tid & 15;
    int lk = tid >> 5, ls = (tid & 31) << 2;
    const float* A = &g_Xr[b][0][0];

    float acc[8][8];
    #pragma unroll
    for (int i = 0; i < 8; i++)
        #pragma unroll
        for (int j = 0; j < 8; j++) acc[i][j] = 0.0f;

    for (int k0 = 0; k0 < KC; k0 += 8) {
        *(float4*)&As[lk][ls] = *(const float4*)&A[(k0 + lk) * Ln + m0 + ls];
        *(float4*)&Bs[lk][ls] = *(const float4*)&A[(k0 + lk) * Ln + n0 + ls];
        __syncthreads();
        #pragma unroll
        for (int kk = 0; kk < 8; kk++) {
            float a[8], bb[8];
            *(float4*)&a[0]  = *(float4*)&As[kk][ty << 2];
            *(float4*)&a[4]  = *(float4*)&As[kk][64 + (ty << 2)];
            *(float4*)&bb[0] = *(float4*)&Bs[kk][tx << 2];
            *(float4*)&bb[4] = *(float4*)&Bs[kk][64 + (tx << 2)];
            #pragma unroll
            for (int i = 0; i < 8; i++)
                #pragma unroll
                for (int j = 0; j < 8; j++) acc[i][j] += a[i] * bb[j];
        }
        __syncthreads();
    }
    #pragma unroll
    for (int i = 0; i < 8; i++) {
        int m = m0 + ((i < 4) ? (ty << 2) + i : 60 + (ty << 2) + i);
        float4 c0 = make_float4(acc[i][0], acc[i][1], acc[i][2], acc[i][3]);
        float4 c1 = make_float4(acc[i][4], acc[i][5], acc[i][6], acc[i][7]);
        *(float4*)&g_G[b][m][n0 + (tx << 2)]      = c0;
        *(float4*)&g_G[b][m][n0 + 64 + (tx << 2)] = c1;
    }
    if (bm != bn) {
        #pragma unroll
        for (int j = 0; j < 8; j++) {
            int n = n0 + ((j < 4) ? (tx << 2) + j : 60 + (tx << 2) + j);
            float4 r0 = make_float4(acc[0][j], acc[1][j], acc[2][j], acc[3][j]);
            float4 r1 = make_float4(acc[4][j], acc[5][j], acc[6][j], acc[7][j]);
            *(float4*)&g_G[b][n][m0 + (ty << 2)]      = r0;
            *(float4*)&g_G[b][n][m0 + 64 + (ty << 2)] = r1;
        }
    }
}

// -------- 9-tap diagonal-shift inner product from G ------------------------
__device__ __forceinline__ float taps9(int b, int p, int q,
                                       int py, int px, int qy, int qx) {
    float acc = 0.0f;
    #pragma unroll
    for (int dy = -1; dy <= 1; dy++)
        #pragma unroll
        for (int dx = -1; dx <= 1; dx++) {
            bool ok = (py + dy >= 0) && (py + dy < HR) && (px + dx >= 0) && (px + dx < HR)
                   && (qy + dy >= 0) && (qy + dy < HR) && (qx + dx >= 0) && (qx + dx < HR);
            if (ok) {
                int off = dy * 64 + dx;
                acc += g_G[b][p + off][q + off];
            }
        }
    return acc;
}

// -------- row factor + diagonal score (softmax reference) ------------------
__global__ void k_diag() {
    int idx = blockIdx.x * blockDim.x + threadIdx.x;
    if (idx >= Bn * Ln) return;
    int p = idx & (Ln - 1);
    int b = idx >> 12;
    int py = p >> 6, px = p & 63;
    float acc = 0.0f;
    #pragma unroll
    for (int dy = -1; dy <= 1; dy++)
        #pragma unroll
        for (int dx = -1; dx <= 1; dx++) {
            int yy = py + dy, xx = px + dx;
            if (yy >= 0 && yy < HR && xx >= 0 && xx < HR) {
                int u = (yy << 6) + xx;
                acc += g_G[b][u][u];
            }
        }
    float w = (10.0f / sqrtf(acc + 0.1152f)) * g_mfilt[b][p];  // 1152*1e-4
    g_w [b][p] = w;
    g_lb[b][p] = w * acc;   // == v_pp (bitwise identical to k_emit's diagonal)
}

// -------- emit surviving softmax terms (one element per thread) ------------
__global__ void __launch_bounds__(256) k_emit() {
    int b = blockIdx.z;
    int p = blockIdx.y;
    int q = (blockIdx.x << 8) + threadIdx.x;
    int py = p >> 6, px = p & 63;
    int qy = q >> 6, qx = q & 63;
    float v = g_w[b][p] * taps9(b, p, q, py, px, qy, qx);
    float d = v - g_lb[b][q];
    if (d > -21.0f) {       // exp(-21) ~ 7.6e-10 vs terms >= exp(-0.02): exact flush
        float e = __expf(fminf(d, 80.0f));
        int slot = atomicAdd(&g_cnt[b][q], 1);
        if (slot < CAP) {
            g_sp_p[b][q][slot] = p;
            g_sp_w[b][q][slot] = e;
        }
    }
}

// -------- patch-value gather straight from x (L2-resident, 16 MB) ----------
__device__ __forceinline__ float vt_val(const float* __restrict__ x,
                                        int b, int p, int f) {
    int c = f >> 4, i = (f >> 2) & 3, j = f & 3;
    int py = p >> 6, px = p & 63;
    int r  = 2 * py - 1 + i;
    int cc = 2 * px - 1 + j;
    return (r >= 0 && r < Hn && cc >= 0 && cc < Wn)
         ? x[((b * Cn + c) * Hn + r) * Wn + cc] : 0.0f;
}

// -------- SpMM: M2[q][:] = sum_k (e_k/sum) * mfilt[p_k] * V[p_k][:] --------
__global__ void __launch_bounds__(256) k_spmm(const float* __restrict__ x) {
    int q = blockIdx.x, b = blockIdx.y;
    int tid = threadIdx.x;
    __shared__ int   s_p[CAP];
    __shared__ float s_w[CAP];
    __shared__ float red[256];
    int cnt = g_cnt[b][q];

    float acc[8];
    #pragma unroll
    for (int i = 0; i < 8; i++) acc[i] = 0.0f;

    if (cnt <= CAP) {
        if (tid < cnt) { s_p[tid] = g_sp_p[b][q][tid]; s_w[tid] = g_sp_w[b][q][tid]; }
        __syncthreads();
        if (tid == 0 && cnt > 1) {        // deterministic order: sort by p (unique)
            for (int i = 1; i < cnt; i++) {
                int   kp = s_p[i]; float kw = s_w[i];
                int j = i - 1;
                while (j >= 0 && s_p[j] > kp) { s_p[j+1] = s_p[j]; s_w[j+1] = s_w[j]; j--; }
                s_p[j+1] = kp; s_w[j+1] = kw;
            }
        }
        __syncthreads();
        float sum = 0.0f;                 // every thread: same fixed order
        for (int k = 0; k < cnt; k++) sum += s_w[k];
        float rsum = 1.0f / sum;
        for (int k = 0; k < cnt; k++) {
            int   p = s_p[k];
            float w = s_w[k] * rsum * g_mfilt[b][p];
            if (w != 0.0f) {
                #pragma unroll
                for (int i = 0; i < 8; i++) acc[i] += w * vt_val(x, b, p, tid + (i << 8));
            }
        }
    } else {
        // exact fallback: recompute all terms from G (never hit for this input)
        int qy = q >> 6, qx = q & 63;
        float lb = g_lb[b][q];
        float part = 0.0f;
        for (int p = tid; p < Ln; p += 256) {
            int py = p >> 6, px = p & 63;
            float d = g_w[b][p] * taps9(b, p, q, py, px, qy, qx) - lb;
            if (d > -21.0f) part += __expf(fminf(d, 80.0f));
        }
        red[tid] = part;
        __syncthreads();
        if (tid == 0) {
            float t = 0.0f;
            for (int i = 0; i < 256; i++) t += red[i];   // deterministic order
            red[0] = t;
        }
        __syncthreads();
        float rsum = 1.0f / red[0];
        __shared__ float sh_e[256];
        for (int p0 = 0; p0 < Ln; p0 += 256) {
            int p = p0 + tid;
            int py = p >> 6, px = p & 63;
            float d = g_w[b][p] * taps9(b, p, q, py, px, qy, qx) - lb;
            sh_e[tid] = (d > -21.0f)
                      ? __expf(fminf(d, 80.0f)) * g_mfilt[b][p] : 0.0f;
            __syncthreads();
            for (int k = 0; k < 256; k++) {
                float w = sh_e[k];
                if (w != 0.0f) {
                    w *= rsum;
                    #pragma unroll
                    for (int i = 0; i < 8; i++)
                        acc[i] += w * vt_val(x, b, p0 + k, tid + (i << 8));
                }
            }
            __syncthreads();
        }
    }
    #pragma unroll
    for (int i = 0; i < 8; i++) g_M2[b][q][tid + (i << 8)] = acc[i];
}

// -------- overlap-add (transposed-conv scatter, gathered) ------------------
__global__ void k_out(float* __restrict__ out) {
    int idx = blockIdx.x * blockDim.x + threadIdx.x;
    if (idx >= Bn * Cn * Hn * Wn) return;
    int X = idx & 127;
    int Y = (idx >> 7) & 127;
    int c = (idx >> 14) & 127;
    int b = idx >> 21;
    int i0 = (Y + 1) & 1, j0 = (X + 1) & 1;
    float acc = 0.0f;
    #pragma unroll
    for (int a = 0; a < 2; a++) {
        int i = i0 + 2 * a;
        int qy = (Y + 1 - i) >> 1;
        if (qy < 0 || qy >= HR) continue;
        #pragma unroll
        for (int e = 0; e < 2; e++) {
            int j = j0 + 2 * e;
            int qx = (X + 1 - j) >> 1;
            if (qx < 0 || qx >= HR) continue;
            acc += g_M2[b][(qy << 6) + qx][(c << 4) + (i << 2) + j];
        }
    }
    out[idx] = 0.25f * acc;
}

// ---------------------------------------------------------------------------
extern "C" void kernel_launch(void* const* d_in, const int* in_sizes, int n_in,
                              void* d_out, int out_size) {
    const float* x    = (const float*)d_in[0];
    const float* mask = (const float*)d_in[1];
    if (n_in >= 2 && in_sizes[0] < in_sizes[1]) {   // defensive: x is the big one
        const float* t = x; x = mask; mask = t;
    }
    float* out = (float*)d_out;

    k_build_xr<<<(Bn * KC * Ln) / 256, 256>>>(x);
    k_mfilt   <<<(Bn * Ln) / 256, 256>>>(mask);

    k_gemm_G  <<<dim3(528, 1, Bn), 256>>>();
    k_diag    <<<(Bn * Ln) / 256, 256>>>();

    k_emit    <<<dim3(Ln / 256, Ln, Bn), 256>>>();

    k_spmm    <<<dim3(Ln, Bn), 256>>>(x);
    k_out     <<<(Bn * Cn * Hn * Wn) / 256, 256>>>(out);
}